// round 14
// baseline (speedup 1.0000x reference)
#include <cuda_runtime.h>
#include <cuda_fp16.h>
#include <cstdint>

#define DINLINE __device__ __forceinline__
static __device__ constexpr float S3 = 0.57735026918962576451f;  // 1/sqrt(3)

// ======================= low-level helpers =======================
DINLINE uint32_t smem_u32(const void* p) {
    uint32_t a;
    asm("{ .reg .u64 t; cvta.to.shared.u64 t, %1; cvt.u32.u64 %0, t; }" : "=r"(a) : "l"(p));
    return a;
}
DINLINE void sts64(uint32_t a, uint32_t lo, uint32_t hi) {
    asm volatile("st.shared.v2.b32 [%0], {%1,%2};" :: "r"(a), "r"(lo), "r"(hi));
}
DINLINE void lds64(uint32_t a, uint32_t& lo, uint32_t& hi) {
    asm volatile("ld.shared.v2.b32 {%0,%1}, [%2];" : "=r"(lo), "=r"(hi) : "r"(a));
}
DINLINE void sts32(uint32_t a, uint32_t v) {
    asm volatile("st.shared.b32 [%0], %1;" :: "r"(a), "r"(v));
}
DINLINE void sts16(uint32_t a, unsigned short v) {
    asm volatile("st.shared.b16 [%0], %1;" :: "r"(a), "h"(v));
}
DINLINE unsigned short lds16(uint32_t a) {
    unsigned short v;
    asm volatile("ld.shared.b16 %0, [%1];" : "=h"(v) : "r"(a));
    return v;
}
DINLINE void ldmx4(uint32_t (&v)[4], uint32_t a) {
    asm volatile("ldmatrix.sync.aligned.m8n8.x4.shared.b16 {%0,%1,%2,%3}, [%4];"
                 : "=r"(v[0]), "=r"(v[1]), "=r"(v[2]), "=r"(v[3]) : "r"(a));
}
DINLINE void mmaf16(float (&d)[4], const uint32_t (&a)[4], uint32_t b0, uint32_t b1) {
    asm volatile(
        "mma.sync.aligned.m16n8k16.row.col.f32.f16.f16.f32 "
        "{%0,%1,%2,%3}, {%4,%5,%6,%7}, {%8,%9}, {%0,%1,%2,%3};"
        : "+f"(d[0]), "+f"(d[1]), "+f"(d[2]), "+f"(d[3])
        : "r"(a[0]), "r"(a[1]), "r"(a[2]), "r"(a[3]), "r"(b0), "r"(b1));
}
// B loads with cache control: cg = L2-only (read-once matrices), nc = L1-cached (hot)
DINLINE uint4 ldg128_cg(const uint4* p) {
    uint4 v;
    asm volatile("ld.global.cg.v4.b32 {%0,%1,%2,%3}, [%4];"
                 : "=r"(v.x), "=r"(v.y), "=r"(v.z), "=r"(v.w) : "l"(p));
    return v;
}
DINLINE uint4 ldg128_nc(const uint4* p) {
    uint4 v;
    asm volatile("ld.global.nc.v4.b32 {%0,%1,%2,%3}, [%4];"
                 : "=r"(v.x), "=r"(v.y), "=r"(v.z), "=r"(v.w) : "l"(p));
    return v;
}
DINLINE uint32_t h2u(__half2 h) { return *reinterpret_cast<uint32_t*>(&h); }
DINLINE __half2  u2h(uint32_t u) { return *reinterpret_cast<__half2*>(&u); }
DINLINE uint32_t pack2(float a, float b) { return h2u(__floats2half2_rn(a, b)); }
DINLINE uint32_t hmul2u(uint32_t a, uint32_t b) { return h2u(__hmul2(u2h(a), u2h(b))); }
DINLINE unsigned short h2us(__half h) { return *reinterpret_cast<unsigned short*>(&h); }
DINLINE float us2f(unsigned short u) { __half h = *reinterpret_cast<__half*>(&u); return __half2float(h); }

// ======================= geometry =======================
// CTA 256 thr = 8 warps; tile 64 rows x 128 w-cols; warp tile 32x32 (grid 2m x 4n).
// X rows in smem: 128 f16 = 256 B = 16 chunks of 16 B, XOR swizzle chunk' = c ^ (row&7).
// Slot 0: X0, then Z. Slots 1..3: X1_i; plane_i reuses slot 1+i.
static constexpr uint32_t SLOT_B = 16896;   // raw X 16384 B; as plane 64 x 132h x 2B
#define SLOT(i) ((uint32_t)(i) * SLOT_B)
static constexpr uint32_t SMEM_TOTAL = 4 * SLOT_B;  // 67584

// Fragment-ordered global weights for direct lane-contiguous LDG.128:
// u32 index = ((j*4+wn)*8+kc)*256 + h*128 + lane*4 + e   (e in 0..3)
//   n = wn*32 + h*16 + ((e>>1)&1)*8 + (lane>>2)
//   k = kc*16 + (e&1)*8 + 2*(lane&3); value = half2(W[k][n], W[k+1][n])
// j: 0=W000, 1=W011, 2=W110, 3=W101 (source [k][n] = src[k*128+n])
__device__ __align__(16) uint32_t g_Wb[4 * 8192];

__global__ void o3tp_prep(const float* __restrict__ W000, const float* __restrict__ W011,
                          const float* __restrict__ W110, const float* __restrict__ W101) {
    int idx = blockIdx.x * blockDim.x + threadIdx.x;  // 0..32767
    int e = idx & 3, lane = (idx >> 2) & 31, h = (idx >> 7) & 1;
    int kc = (idx >> 8) & 7, wn = (idx >> 11) & 3, j = idx >> 13;
    int n = wn * 32 + h * 16 + ((e >> 1) & 1) * 8 + (lane >> 2);
    int k = kc * 16 + (e & 1) * 8 + 2 * (lane & 3);
    const float* src = (j == 0) ? W000 : (j == 1) ? W011 : (j == 2) ? W110 : W101;
    g_Wb[idx] = pack2(src[k * 128 + n], src[(k + 1) * 128 + n]);
}

// ======================= X fills (warp-per-row, lane-contiguous LDG) ==========
DINLINE void fill_x0(uint32_t slot, const float* __restrict__ x, long row0, int n,
                     int wid, int lane) {
    #pragma unroll
    for (int it = 0; it < 8; ++it) {
        int r = it * 8 + wid;
        long gr = row0 + r;
        float4 xv = (gr < (long)n) ? ((const float4*)(x + gr * 512))[lane]
                                   : make_float4(0.f, 0.f, 0.f, 0.f);
        uint32_t a = slot + (uint32_t)r * 256u
                   + ((((uint32_t)lane >> 1) ^ (uint32_t)(r & 7)) << 4)
                   + (uint32_t)(lane & 1) * 8u;
        sts64(a, pack2(xv.x, xv.y), pack2(xv.z, xv.w));
    }
}
// X1: proven R7 scatter into slots 1..3 (warp-per-row, lane-contiguous LDG)
DINLINE void fill_x1(uint32_t sb, const float* __restrict__ x, long row0, int n,
                     int wid, int lane) {
    #pragma unroll
    for (int it = 0; it < 8; ++it) {
        int r = it * 8 + wid;
        long gr = row0 + r;
        bool v = gr < (long)n;
        const float4* src = (const float4*)(x + gr * 512 + 128);
        uint32_t rowb = (uint32_t)r * 256u, s = (uint32_t)(r & 7);
        #pragma unroll
        for (int m = 0; m < 3; ++m) {
            float4 xv = v ? src[m * 32 + lane] : make_float4(0.f, 0.f, 0.f, 0.f);
            float el[4] = {xv.x, xv.y, xv.z, xv.w};
            #pragma unroll
            for (int j = 0; j < 4; ++j) {
                uint32_t e = (uint32_t)(m * 128 + lane * 4 + j);
                uint32_t u = (e * 21846u) >> 16;     // e/3
                uint32_t i = e - 3u * u;             // e%3
                uint32_t a = sb + (1u + i) * SLOT_B + rowb
                           + ((((u >> 3) & 15u) ^ s) << 4) + (u & 7u) * 2u;
                sts16(a, h2us(__float2half_rn(el[j])));
            }
        }
    }
}
// Z pass: Z[r][u] = S3*(y1_0*X1_0 + y1_1*X1_1 + y1_2*X1_2)[r][u] -> slot 0.
// Warp-per-row on the SAME rows this warp just filled (warp-local dependency).
DINLINE void compute_z(uint32_t sb, const float* __restrict__ y, long row0, int n,
                       int wid, int lane) {
    #pragma unroll
    for (int it = 0; it < 8; ++it) {
        int r = it * 8 + wid;
        long gr = row0 + r;
        bool v = gr < (long)n;
        float4 yld = v ? *(const float4*)(y + gr * 4) : make_float4(0.f, 0.f, 0.f, 0.f);
        float ya = S3 * yld.y, yb = S3 * yld.z, yc = S3 * yld.w;
        // u0 = lane*4 -> chunk = lane>>1, byte offset within chunk = (lane&1)*8
        uint32_t off = (uint32_t)r * 256u
                     + ((((uint32_t)lane >> 1) ^ (uint32_t)(r & 7)) << 4)
                     + (uint32_t)(lane & 1) * 8u;
        uint32_t lo1, hi1, lo2, hi2, lo3, hi3;
        lds64(sb + SLOT(1) + off, lo1, hi1);
        lds64(sb + SLOT(2) + off, lo2, hi2);
        lds64(sb + SLOT(3) + off, lo3, hi3);
        float2 a0 = __half22float2(u2h(lo1)), a1 = __half22float2(u2h(hi1));
        float2 b0 = __half22float2(u2h(lo2)), b1 = __half22float2(u2h(hi2));
        float2 c0 = __half22float2(u2h(lo3)), c1 = __half22float2(u2h(hi3));
        float z0 = ya * a0.x + yb * b0.x + yc * c0.x;
        float z1 = ya * a0.y + yb * b0.y + yc * c0.y;
        float z2 = ya * a1.x + yb * b1.x + yc * c1.x;
        float z3 = ya * a1.y + yb * b1.y + yc * c1.y;
        sts64(sb + SLOT(0) + off, pack2(z0, z1), pack2(z2, z3));
    }
}

// ======================= GEMMs (64x128 out, K=128) =======================
// dual: acc1 += (c1 .* A) @ B1;  acc2 += A @ B2. A read once. B via cg (read-once).
DINLINE void dual64(uint32_t xslot, const uint4* __restrict__ pB1,
                    const uint4* __restrict__ pB2,
                    const uint32_t (&c1)[2][2],
                    float (&acc1)[2][4][4], float (&acc2)[2][4][4],
                    int wm, int lane) {
    const uint32_t rA = (uint32_t)(wm * 32 + (lane & 15));
    const uint32_t cA = (uint32_t)((lane >> 4) & 1);
    const uint32_t sA = rA & 7;
    const uint32_t bA0 = xslot + rA * 256u, bA1 = bA0 + 4096u;
    #pragma unroll
    for (int kc = 0; kc < 8; ++kc) {
        uint32_t a0[4], a1[4];
        uint32_t ka = (((((uint32_t)kc << 1) | cA) ^ sA) << 4);
        ldmx4(a0, bA0 + ka); ldmx4(a1, bA1 + ka);
        uint4 p = ldg128_cg(pB1 + kc * 64), q = ldg128_cg(pB1 + kc * 64 + 32);
        uint4 r = ldg128_cg(pB2 + kc * 64), s = ldg128_cg(pB2 + kc * 64 + 32);
        uint32_t t0[4], t1[4];
        t0[0] = hmul2u(a0[0], c1[0][0]); t0[1] = hmul2u(a0[1], c1[0][1]);
        t0[2] = hmul2u(a0[2], c1[0][0]); t0[3] = hmul2u(a0[3], c1[0][1]);
        t1[0] = hmul2u(a1[0], c1[1][0]); t1[1] = hmul2u(a1[1], c1[1][1]);
        t1[2] = hmul2u(a1[2], c1[1][0]); t1[3] = hmul2u(a1[3], c1[1][1]);
        mmaf16(acc1[0][0], t0, p.x, p.y); mmaf16(acc1[0][1], t0, p.z, p.w);
        mmaf16(acc1[0][2], t0, q.x, q.y); mmaf16(acc1[0][3], t0, q.z, q.w);
        mmaf16(acc1[1][0], t1, p.x, p.y); mmaf16(acc1[1][1], t1, p.z, p.w);
        mmaf16(acc1[1][2], t1, q.x, q.y); mmaf16(acc1[1][3], t1, q.z, q.w);
        mmaf16(acc2[0][0], a0, r.x, r.y); mmaf16(acc2[0][1], a0, r.z, r.w);
        mmaf16(acc2[0][2], a0, s.x, s.y); mmaf16(acc2[0][3], a0, s.z, s.w);
        mmaf16(acc2[1][0], a1, r.x, r.y); mmaf16(acc2[1][1], a1, r.z, r.w);
        mmaf16(acc2[1][2], a1, s.x, s.y); mmaf16(acc2[1][3], a1, s.z, s.w);
    }
}
// single: acc += (SC ? (c .* A) : A) @ B. CG selects L2-only vs L1-cached B loads.
template <bool SC, bool CG>
DINLINE void single64(uint32_t xslot, const uint4* __restrict__ pB,
                      const uint32_t (&c)[2][2], float (&acc)[2][4][4],
                      int wm, int lane) {
    const uint32_t rA = (uint32_t)(wm * 32 + (lane & 15));
    const uint32_t cA = (uint32_t)((lane >> 4) & 1);
    const uint32_t sA = rA & 7;
    const uint32_t bA0 = xslot + rA * 256u, bA1 = bA0 + 4096u;
    #pragma unroll
    for (int kc = 0; kc < 8; ++kc) {
        uint32_t a0[4], a1[4];
        uint32_t ka = (((((uint32_t)kc << 1) | cA) ^ sA) << 4);
        ldmx4(a0, bA0 + ka); ldmx4(a1, bA1 + ka);
        uint4 p = CG ? ldg128_cg(pB + kc * 64) : ldg128_nc(pB + kc * 64);
        uint4 q = CG ? ldg128_cg(pB + kc * 64 + 32) : ldg128_nc(pB + kc * 64 + 32);
        if (SC) {
            uint32_t t0[4], t1[4];
            t0[0] = hmul2u(a0[0], c[0][0]); t0[1] = hmul2u(a0[1], c[0][1]);
            t0[2] = hmul2u(a0[2], c[0][0]); t0[3] = hmul2u(a0[3], c[0][1]);
            t1[0] = hmul2u(a1[0], c[1][0]); t1[1] = hmul2u(a1[1], c[1][1]);
            t1[2] = hmul2u(a1[2], c[1][0]); t1[3] = hmul2u(a1[3], c[1][1]);
            mmaf16(acc[0][0], t0, p.x, p.y); mmaf16(acc[0][1], t0, p.z, p.w);
            mmaf16(acc[0][2], t0, q.x, q.y); mmaf16(acc[0][3], t0, q.z, q.w);
            mmaf16(acc[1][0], t1, p.x, p.y); mmaf16(acc[1][1], t1, p.z, p.w);
            mmaf16(acc[1][2], t1, q.x, q.y); mmaf16(acc[1][3], t1, q.z, q.w);
        } else {
            mmaf16(acc[0][0], a0, p.x, p.y); mmaf16(acc[0][1], a0, p.z, p.w);
            mmaf16(acc[0][2], a0, q.x, q.y); mmaf16(acc[0][3], a0, q.z, q.w);
            mmaf16(acc[1][0], a1, p.x, p.y); mmaf16(acc[1][1], a1, p.z, p.w);
            mmaf16(acc[1][2], a1, q.x, q.y); mmaf16(acc[1][3], a1, q.z, q.w);
        }
    }
}
DINLINE void zacc(float (&a)[2][4][4]) {
    #pragma unroll
    for (int m = 0; m < 2; ++m)
        #pragma unroll
        for (int g = 0; g < 4; ++g)
            #pragma unroll
            for (int e = 0; e < 4; ++e) a[m][g][e] = 0.0f;
}

// ======================= main kernel =======================
__global__ void __launch_bounds__(256, 2) o3tp_main(
    const float* __restrict__ x, const float* __restrict__ y,
    const float* __restrict__ bias, float* __restrict__ out, int n)
{
    extern __shared__ char smem[];
    const uint32_t sb = smem_u32(smem);
    const int t = threadIdx.x, lane = t & 31, wid = t >> 5;
    const int wm = wid & 1, wn = wid >> 1;
    const long row0 = (long)blockIdx.x * 64;

    fill_x0(sb + SLOT(0), x, row0, n, wid, lane);

    // per-thread c-frag rows & y values (overlaps X0 fill LDG latency)
    int rl[2]; long gr0[2]; bool va[2], vb[2];
    float yv[2][2][4];
    #pragma unroll
    for (int mf = 0; mf < 2; ++mf) {
        rl[mf] = wm * 32 + mf * 16 + (lane >> 2);
        gr0[mf] = row0 + rl[mf];
        va[mf] = gr0[mf] < (long)n;
        vb[mf] = gr0[mf] + 8 < (long)n;
        #pragma unroll
        for (int e = 0; e < 4; ++e) { yv[mf][0][e] = 0.f; yv[mf][1][e] = 0.f; }
        if (va[mf]) { float4 v = *(const float4*)(y + gr0[mf] * 4);
            yv[mf][0][0] = v.x; yv[mf][0][1] = v.y; yv[mf][0][2] = v.z; yv[mf][0][3] = v.w; }
        if (vb[mf]) { float4 v = *(const float4*)(y + (gr0[mf] + 8) * 4);
            yv[mf][1][0] = v.x; yv[mf][1][1] = v.y; yv[mf][1][2] = v.z; yv[mf][1][3] = v.w; }
    }

    // scale constants (half2 broadcast)
    uint32_t y0h[2][2], s3y0h[2][2];
    #pragma unroll
    for (int mf = 0; mf < 2; ++mf)
        #pragma unroll
        for (int h = 0; h < 2; ++h) {
            y0h[mf][h]   = h2u(__float2half2_rn(yv[mf][h][0]));
            s3y0h[mf][h] = h2u(__float2half2_rn(S3 * yv[mf][h][0]));
        }

    // warp B-fragment pointers (uint4 units): matrix j at j*2048, wn at wn*512
    const uint4* wbase = (const uint4*)g_Wb;
    const uint4* pW000 = wbase + 0 * 2048 + wn * 512 + lane;
    const uint4* pW011 = wbase + 1 * 2048 + wn * 512 + lane;
    const uint4* pW110 = wbase + 2 * 2048 + wn * 512 + lane;
    const uint4* pW101 = wbase + 3 * 2048 + wn * 512 + lane;

    float o0[2][4][4], aux[2][4][4];
    zacc(o0); zacc(aux);
    __syncthreads();   // X0 visible

    // ---- phase 1: o0 += (y0*X0)@W000 ; p011 = X0@W011  (X0 = slot0) ----
    dual64(sb + SLOT(0), pW000, pW011, y0h, o0, aux, wm, lane);

    // compress p011 to 16 half2 regs
    uint32_t p011h[16];
    #pragma unroll
    for (int mf = 0; mf < 2; ++mf)
        #pragma unroll
        for (int g = 0; g < 4; ++g) {
            p011h[mf * 8 + g * 2 + 0] = pack2(aux[mf][g][0], aux[mf][g][1]);
            p011h[mf * 8 + g * 2 + 1] = pack2(aux[mf][g][2], aux[mf][g][3]);
        }

    __syncthreads();                         // all warps done reading X0 (slot 0)
    fill_x1(sb, x, row0, n, wid, lane);      // X1_0/1/2 -> slots 1..3
    __syncwarp();                            // warp-local: fills visible to Z pass
    compute_z(sb, y, row0, n, wid, lane);    // Z -> slot 0 (same rows, same warp)
    __syncthreads();                         // all fills + Z visible CTA-wide

    // ---- phase 2a: o0 += Z @ W110  (Z prescaled with S3*y1, no hmul) ----
    single64<false, true>(sb + SLOT(0), pW110, y0h, o0, wm, lane);

    // ---- phase 2b: per i: o1_i = S3*y1_i*p011 + (S3*y0*X1_i)@W101 -> plane_i ----
    #pragma unroll 1
    for (int i = 0; i < 3; ++i) {
        float s1[2][2];
        #pragma unroll
        for (int mf = 0; mf < 2; ++mf)
            #pragma unroll
            for (int h = 0; h < 2; ++h)
                s1[mf][h] = S3 * yv[mf][h][1 + i];
        // seed aux = S3*y1_i * p011
        #pragma unroll
        for (int mf = 0; mf < 2; ++mf)
            #pragma unroll
            for (int g = 0; g < 4; ++g) {
                float2 plo = __half22float2(u2h(p011h[mf * 8 + g * 2 + 0]));
                float2 phi = __half22float2(u2h(p011h[mf * 8 + g * 2 + 1]));
                aux[mf][g][0] = s1[mf][0] * plo.x; aux[mf][g][1] = s1[mf][0] * plo.y;
                aux[mf][g][2] = s1[mf][1] * phi.x; aux[mf][g][3] = s1[mf][1] * phi.y;
            }
        single64<true, false>(sb + SLOT(1 + i), pW101, s3y0h, aux, wm, lane);
        __syncthreads();  // all warps done reading slot 1+i before overwrite
        // stage o1_i as f16 plane (pitch 132 halves) into slot 1+i
        #pragma unroll
        for (int mf = 0; mf < 2; ++mf)
            #pragma unroll
            for (int g = 0; g < 4; ++g) {
                uint32_t w0 = (uint32_t)(wn * 32 + g * 8 + 2 * (lane & 3));
                sts32(sb + SLOT(1 + i) + ((uint32_t)rl[mf] * 132u + w0) * 2u,
                      pack2(aux[mf][g][0], aux[mf][g][1]));
                sts32(sb + SLOT(1 + i) + ((uint32_t)(rl[mf] + 8) * 132u + w0) * 2u,
                      pack2(aux[mf][g][2], aux[mf][g][3]));
            }
    }

    // ---- store o0 + bias (float2, frag-direct) ----
    #pragma unroll
    for (int mf = 0; mf < 2; ++mf)
        #pragma unroll
        for (int g = 0; g < 4; ++g) {
            const int w0 = wn * 32 + g * 8 + 2 * (lane & 3);
            const float b0 = __ldg(bias + w0), b1 = __ldg(bias + w0 + 1);
            if (va[mf]) { float2 o = make_float2(o0[mf][g][0] + b0, o0[mf][g][1] + b1);
                          *(float2*)(out + gr0[mf] * 512 + w0) = o; }
            if (vb[mf]) { float2 o = make_float2(o0[mf][g][2] + b0, o0[mf][g][3] + b1);
                          *(float2*)(out + (gr0[mf] + 8) * 512 + w0) = o; }
        }
    __syncthreads();   // planes complete before final interleave

    // ---- final: interleave planes -> out[:, 128:512], warp-per-row STG.128 ----
    #pragma unroll 1
    for (int it = 0; it < 8; ++it) {
        int r = it * 8 + wid;
        long gr = row0 + r;
        if (gr < (long)n) {
            float4* dst = (float4*)(out + gr * 512 + 128);
            uint32_t pb = sb + (uint32_t)r * 264u;
            #pragma unroll
            for (int m = 0; m < 3; ++m) {
                uint32_t e0 = (uint32_t)(m * 128 + lane * 4);
                float o[4];
                #pragma unroll
                for (int j = 0; j < 4; ++j) {
                    uint32_t e = e0 + j;
                    uint32_t u = (e * 21846u) >> 16;   // e/3
                    uint32_t i = e - 3u * u;           // e%3
                    o[j] = us2f(lds16(pb + (1u + i) * SLOT_B + u * 2u));
                }
                dst[m * 32 + lane] = make_float4(o[0], o[1], o[2], o[3]);
            }
        }
    }
}

// ======================= launch =======================
extern "C" void kernel_launch(void* const* d_in, const int* in_sizes, int n_in,
                              void* d_out, int out_size) {
    const float* x    = (const float*)d_in[0];
    const float* y    = (const float*)d_in[1];
    const float* W000 = (const float*)d_in[2];
    const float* W011 = (const float*)d_in[3];
    const float* W101 = (const float*)d_in[4];
    const float* W110 = (const float*)d_in[5];
    const float* bias = (const float*)d_in[6];

    int n = in_sizes[1] / 4;  // y is (n, 4)
    if (n <= 0) return;

    o3tp_prep<<<128, 256>>>(W000, W011, W110, W101);

    cudaFuncSetAttribute(o3tp_main, cudaFuncAttributeMaxDynamicSharedMemorySize, SMEM_TOTAL);
    int grid = (n + 63) / 64;
    o3tp_main<<<grid, 256, SMEM_TOTAL>>>(x, y, bias, (float*)d_out, n);
}

// round 15
// speedup vs baseline: 1.3426x; 1.3426x over previous
#include <cuda_runtime.h>
#include <cuda_fp16.h>
#include <cstdint>

#define DINLINE __device__ __forceinline__
static __device__ constexpr float S3 = 0.57735026918962576451f;  // 1/sqrt(3)

// ======================= low-level helpers =======================
DINLINE uint32_t smem_u32(const void* p) {
    uint32_t a;
    asm("{ .reg .u64 t; cvta.to.shared.u64 t, %1; cvt.u32.u64 %0, t; }" : "=r"(a) : "l"(p));
    return a;
}
DINLINE void sts64(uint32_t a, uint32_t lo, uint32_t hi) {
    asm volatile("st.shared.v2.b32 [%0], {%1,%2};" :: "r"(a), "r"(lo), "r"(hi));
}
DINLINE void lds64(uint32_t a, uint32_t& lo, uint32_t& hi) {
    asm volatile("ld.shared.v2.b32 {%0,%1}, [%2];" : "=r"(lo), "=r"(hi) : "r"(a));
}
DINLINE void sts32(uint32_t a, uint32_t v) {
    asm volatile("st.shared.b32 [%0], %1;" :: "r"(a), "r"(v));
}
DINLINE void sts16(uint32_t a, unsigned short v) {
    asm volatile("st.shared.b16 [%0], %1;" :: "r"(a), "h"(v));
}
DINLINE unsigned short lds16(uint32_t a) {
    unsigned short v;
    asm volatile("ld.shared.b16 %0, [%1];" : "=h"(v) : "r"(a));
    return v;
}
DINLINE void ldmx4(uint32_t (&v)[4], uint32_t a) {
    asm volatile("ldmatrix.sync.aligned.m8n8.x4.shared.b16 {%0,%1,%2,%3}, [%4];"
                 : "=r"(v[0]), "=r"(v[1]), "=r"(v[2]), "=r"(v[3]) : "r"(a));
}
DINLINE void mmaf16(float (&d)[4], const uint32_t (&a)[4], uint32_t b0, uint32_t b1) {
    asm volatile(
        "mma.sync.aligned.m16n8k16.row.col.f32.f16.f16.f32 "
        "{%0,%1,%2,%3}, {%4,%5,%6,%7}, {%8,%9}, {%0,%1,%2,%3};"
        : "+f"(d[0]), "+f"(d[1]), "+f"(d[2]), "+f"(d[3])
        : "r"(a[0]), "r"(a[1]), "r"(a[2]), "r"(a[3]), "r"(b0), "r"(b1));
}
// B loads: nc = L1-cached read-only path (the ONLY fast path for hot B frags)
DINLINE uint4 ldg128_nc(const uint4* p) {
    uint4 v;
    asm volatile("ld.global.nc.v4.b32 {%0,%1,%2,%3}, [%4];"
                 : "=r"(v.x), "=r"(v.y), "=r"(v.z), "=r"(v.w) : "l"(p));
    return v;
}
DINLINE uint32_t h2u(__half2 h) { return *reinterpret_cast<uint32_t*>(&h); }
DINLINE __half2  u2h(uint32_t u) { return *reinterpret_cast<__half2*>(&u); }
DINLINE uint32_t pack2(float a, float b) { return h2u(__floats2half2_rn(a, b)); }
DINLINE uint32_t hmul2u(uint32_t a, uint32_t b) { return h2u(__hmul2(u2h(a), u2h(b))); }
DINLINE unsigned short h2us(__half h) { return *reinterpret_cast<unsigned short*>(&h); }
DINLINE float us2f(unsigned short u) { __half h = *reinterpret_cast<__half*>(&u); return __half2float(h); }

// ======================= geometry =======================
// CTA 256 thr = 8 warps; tile 64 rows x 128 w-cols; warp tile 32x32 (grid 2m x 4n).
// X rows in smem: 128 f16 = 256 B = 16 chunks of 16 B, XOR swizzle chunk' = c ^ (row&7).
// Slot 0: X0, then Z. Slots 1..3: X1_i; plane_i reuses slot 1+i.
static constexpr uint32_t SLOT_B = 16896;   // raw X 16384 B; as plane 64 x 132h x 2B
#define SLOT(i) ((uint32_t)(i) * SLOT_B)
static constexpr uint32_t SMEM_TOTAL = 4 * SLOT_B;  // 67584

// Fragment-ordered global weights for direct lane-contiguous LDG.128:
// u32 index = ((j*4+wn)*8+kc)*256 + h*128 + lane*4 + e   (e in 0..3)
//   n = wn*32 + h*16 + ((e>>1)&1)*8 + (lane>>2)
//   k = kc*16 + (e&1)*8 + 2*(lane&3); value = half2(W[k][n], W[k+1][n])
// j: 0=W000, 1=W011, 2=W110, 3=W101 (source [k][n] = src[k*128+n])
__device__ __align__(16) uint32_t g_Wb[4 * 8192];

__global__ void o3tp_prep(const float* __restrict__ W000, const float* __restrict__ W011,
                          const float* __restrict__ W110, const float* __restrict__ W101) {
    int idx = blockIdx.x * blockDim.x + threadIdx.x;  // 0..32767
    int e = idx & 3, lane = (idx >> 2) & 31, h = (idx >> 7) & 1;
    int kc = (idx >> 8) & 7, wn = (idx >> 11) & 3, j = idx >> 13;
    int n = wn * 32 + h * 16 + ((e >> 1) & 1) * 8 + (lane >> 2);
    int k = kc * 16 + (e & 1) * 8 + 2 * (lane & 3);
    const float* src = (j == 0) ? W000 : (j == 1) ? W011 : (j == 2) ? W110 : W101;
    g_Wb[idx] = pack2(src[k * 128 + n], src[(k + 1) * 128 + n]);
}

// ======================= X fills (warp-per-row, lane-contiguous LDG) ==========
DINLINE void fill_x0(uint32_t slot, const float* __restrict__ x, long row0, int n,
                     int wid, int lane) {
    #pragma unroll
    for (int it = 0; it < 8; ++it) {
        int r = it * 8 + wid;
        long gr = row0 + r;
        float4 xv = (gr < (long)n) ? ((const float4*)(x + gr * 512))[lane]
                                   : make_float4(0.f, 0.f, 0.f, 0.f);
        uint32_t a = slot + (uint32_t)r * 256u
                   + ((((uint32_t)lane >> 1) ^ (uint32_t)(r & 7)) << 4)
                   + (uint32_t)(lane & 1) * 8u;
        sts64(a, pack2(xv.x, xv.y), pack2(xv.z, xv.w));
    }
}
// X1: proven scatter into slots 1..3 (warp-per-row, lane-contiguous LDG)
DINLINE void fill_x1(uint32_t sb, const float* __restrict__ x, long row0, int n,
                     int wid, int lane) {
    #pragma unroll
    for (int it = 0; it < 8; ++it) {
        int r = it * 8 + wid;
        long gr = row0 + r;
        bool v = gr < (long)n;
        const float4* src = (const float4*)(x + gr * 512 + 128);
        uint32_t rowb = (uint32_t)r * 256u, s = (uint32_t)(r & 7);
        #pragma unroll
        for (int m = 0; m < 3; ++m) {
            float4 xv = v ? src[m * 32 + lane] : make_float4(0.f, 0.f, 0.f, 0.f);
            float el[4] = {xv.x, xv.y, xv.z, xv.w};
            #pragma unroll
            for (int j = 0; j < 4; ++j) {
                uint32_t e = (uint32_t)(m * 128 + lane * 4 + j);
                uint32_t u = (e * 21846u) >> 16;     // e/3
                uint32_t i = e - 3u * u;             // e%3
                uint32_t a = sb + (1u + i) * SLOT_B + rowb
                           + ((((u >> 3) & 15u) ^ s) << 4) + (u & 7u) * 2u;
                sts16(a, h2us(__float2half_rn(el[j])));
            }
        }
    }
}
// Z pass: Z[r][u] = S3*(y1_0*X1_0 + y1_1*X1_1 + y1_2*X1_2)[r][u] -> slot 0.
// Warp-per-row on the SAME rows this warp just filled (warp-local dependency).
DINLINE void compute_z(uint32_t sb, const float* __restrict__ y, long row0, int n,
                       int wid, int lane) {
    #pragma unroll
    for (int it = 0; it < 8; ++it) {
        int r = it * 8 + wid;
        long gr = row0 + r;
        bool v = gr < (long)n;
        float4 yld = v ? *(const float4*)(y + gr * 4) : make_float4(0.f, 0.f, 0.f, 0.f);
        float ya = S3 * yld.y, yb = S3 * yld.z, yc = S3 * yld.w;
        uint32_t off = (uint32_t)r * 256u
                     + ((((uint32_t)lane >> 1) ^ (uint32_t)(r & 7)) << 4)
                     + (uint32_t)(lane & 1) * 8u;
        uint32_t lo1, hi1, lo2, hi2, lo3, hi3;
        lds64(sb + SLOT(1) + off, lo1, hi1);
        lds64(sb + SLOT(2) + off, lo2, hi2);
        lds64(sb + SLOT(3) + off, lo3, hi3);
        float2 a0 = __half22float2(u2h(lo1)), a1 = __half22float2(u2h(hi1));
        float2 b0 = __half22float2(u2h(lo2)), b1 = __half22float2(u2h(hi2));
        float2 c0 = __half22float2(u2h(lo3)), c1 = __half22float2(u2h(hi3));
        float z0 = ya * a0.x + yb * b0.x + yc * c0.x;
        float z1 = ya * a0.y + yb * b0.y + yc * c0.y;
        float z2 = ya * a1.x + yb * b1.x + yc * c1.x;
        float z3 = ya * a1.y + yb * b1.y + yc * c1.y;
        sts64(sb + SLOT(0) + off, pack2(z0, z1), pack2(z2, z3));
    }
}

// ======================= GEMMs (64x128 out, K=128) =======================
// dual: acc1 += (c1 .* A) @ B1;  acc2 += A @ B2. A read once; B via nc (L1).
DINLINE void dual64(uint32_t xslot, const uint4* __restrict__ pB1,
                    const uint4* __restrict__ pB2,
                    const uint32_t (&c1)[2][2],
                    float (&acc1)[2][4][4], float (&acc2)[2][4][4],
                    int wm, int lane) {
    const uint32_t rA = (uint32_t)(wm * 32 + (lane & 15));
    const uint32_t cA = (uint32_t)((lane >> 4) & 1);
    const uint32_t sA = rA & 7;
    const uint32_t bA0 = xslot + rA * 256u, bA1 = bA0 + 4096u;
    #pragma unroll
    for (int kc = 0; kc < 8; ++kc) {
        uint32_t a0[4], a1[4];
        uint32_t ka = (((((uint32_t)kc << 1) | cA) ^ sA) << 4);
        ldmx4(a0, bA0 + ka); ldmx4(a1, bA1 + ka);
        uint4 p = ldg128_nc(pB1 + kc * 64), q = ldg128_nc(pB1 + kc * 64 + 32);
        uint4 r = ldg128_nc(pB2 + kc * 64), s = ldg128_nc(pB2 + kc * 64 + 32);
        uint32_t t0[4], t1[4];
        t0[0] = hmul2u(a0[0], c1[0][0]); t0[1] = hmul2u(a0[1], c1[0][1]);
        t0[2] = hmul2u(a0[2], c1[0][0]); t0[3] = hmul2u(a0[3], c1[0][1]);
        t1[0] = hmul2u(a1[0], c1[1][0]); t1[1] = hmul2u(a1[1], c1[1][1]);
        t1[2] = hmul2u(a1[2], c1[1][0]); t1[3] = hmul2u(a1[3], c1[1][1]);
        mmaf16(acc1[0][0], t0, p.x, p.y); mmaf16(acc1[0][1], t0, p.z, p.w);
        mmaf16(acc1[0][2], t0, q.x, q.y); mmaf16(acc1[0][3], t0, q.z, q.w);
        mmaf16(acc1[1][0], t1, p.x, p.y); mmaf16(acc1[1][1], t1, p.z, p.w);
        mmaf16(acc1[1][2], t1, q.x, q.y); mmaf16(acc1[1][3], t1, q.z, q.w);
        mmaf16(acc2[0][0], a0, r.x, r.y); mmaf16(acc2[0][1], a0, r.z, r.w);
        mmaf16(acc2[0][2], a0, s.x, s.y); mmaf16(acc2[0][3], a0, s.z, s.w);
        mmaf16(acc2[1][0], a1, r.x, r.y); mmaf16(acc2[1][1], a1, r.z, r.w);
        mmaf16(acc2[1][2], a1, s.x, s.y); mmaf16(acc2[1][3], a1, s.z, s.w);
    }
}
// single: acc += (SC ? (c .* A) : A) @ B. B via nc (L1-cached).
template <bool SC>
DINLINE void single64(uint32_t xslot, const uint4* __restrict__ pB,
                      const uint32_t (&c)[2][2], float (&acc)[2][4][4],
                      int wm, int lane) {
    const uint32_t rA = (uint32_t)(wm * 32 + (lane & 15));
    const uint32_t cA = (uint32_t)((lane >> 4) & 1);
    const uint32_t sA = rA & 7;
    const uint32_t bA0 = xslot + rA * 256u, bA1 = bA0 + 4096u;
    #pragma unroll
    for (int kc = 0; kc < 8; ++kc) {
        uint32_t a0[4], a1[4];
        uint32_t ka = (((((uint32_t)kc << 1) | cA) ^ sA) << 4);
        ldmx4(a0, bA0 + ka); ldmx4(a1, bA1 + ka);
        uint4 p = ldg128_nc(pB + kc * 64);
        uint4 q = ldg128_nc(pB + kc * 64 + 32);
        if (SC) {
            uint32_t t0[4], t1[4];
            t0[0] = hmul2u(a0[0], c[0][0]); t0[1] = hmul2u(a0[1], c[0][1]);
            t0[2] = hmul2u(a0[2], c[0][0]); t0[3] = hmul2u(a0[3], c[0][1]);
            t1[0] = hmul2u(a1[0], c[1][0]); t1[1] = hmul2u(a1[1], c[1][1]);
            t1[2] = hmul2u(a1[2], c[1][0]); t1[3] = hmul2u(a1[3], c[1][1]);
            mmaf16(acc[0][0], t0, p.x, p.y); mmaf16(acc[0][1], t0, p.z, p.w);
            mmaf16(acc[0][2], t0, q.x, q.y); mmaf16(acc[0][3], t0, q.z, q.w);
            mmaf16(acc[1][0], t1, p.x, p.y); mmaf16(acc[1][1], t1, p.z, p.w);
            mmaf16(acc[1][2], t1, q.x, q.y); mmaf16(acc[1][3], t1, q.z, q.w);
        } else {
            mmaf16(acc[0][0], a0, p.x, p.y); mmaf16(acc[0][1], a0, p.z, p.w);
            mmaf16(acc[0][2], a0, q.x, q.y); mmaf16(acc[0][3], a0, q.z, q.w);
            mmaf16(acc[1][0], a1, p.x, p.y); mmaf16(acc[1][1], a1, p.z, p.w);
            mmaf16(acc[1][2], a1, q.x, q.y); mmaf16(acc[1][3], a1, q.z, q.w);
        }
    }
}
DINLINE void zacc(float (&a)[2][4][4]) {
    #pragma unroll
    for (int m = 0; m < 2; ++m)
        #pragma unroll
        for (int g = 0; g < 4; ++g)
            #pragma unroll
            for (int e = 0; e < 4; ++e) a[m][g][e] = 0.0f;
}

// ======================= main kernel =======================
__global__ void __launch_bounds__(256, 2) o3tp_main(
    const float* __restrict__ x, const float* __restrict__ y,
    const float* __restrict__ bias, float* __restrict__ out, int n)
{
    extern __shared__ char smem[];
    const uint32_t sb = smem_u32(smem);
    const int t = threadIdx.x, lane = t & 31, wid = t >> 5;
    const int wm = wid & 1, wn = wid >> 1;
    const long row0 = (long)blockIdx.x * 64;

    fill_x0(sb + SLOT(0), x, row0, n, wid, lane);

    // per-thread c-frag rows & y values (overlaps X0 fill LDG latency)
    int rl[2]; long gr0[2]; bool va[2], vb[2];
    float yv[2][2][4];
    #pragma unroll
    for (int mf = 0; mf < 2; ++mf) {
        rl[mf] = wm * 32 + mf * 16 + (lane >> 2);
        gr0[mf] = row0 + rl[mf];
        va[mf] = gr0[mf] < (long)n;
        vb[mf] = gr0[mf] + 8 < (long)n;
        #pragma unroll
        for (int e = 0; e < 4; ++e) { yv[mf][0][e] = 0.f; yv[mf][1][e] = 0.f; }
        if (va[mf]) { float4 v = *(const float4*)(y + gr0[mf] * 4);
            yv[mf][0][0] = v.x; yv[mf][0][1] = v.y; yv[mf][0][2] = v.z; yv[mf][0][3] = v.w; }
        if (vb[mf]) { float4 v = *(const float4*)(y + (gr0[mf] + 8) * 4);
            yv[mf][1][0] = v.x; yv[mf][1][1] = v.y; yv[mf][1][2] = v.z; yv[mf][1][3] = v.w; }
    }

    // scale constants (half2 broadcast)
    uint32_t y0h[2][2], s3y0h[2][2];
    #pragma unroll
    for (int mf = 0; mf < 2; ++mf)
        #pragma unroll
        for (int h = 0; h < 2; ++h) {
            y0h[mf][h]   = h2u(__float2half2_rn(yv[mf][h][0]));
            s3y0h[mf][h] = h2u(__float2half2_rn(S3 * yv[mf][h][0]));
        }

    // warp B-fragment pointers (uint4 units): matrix j at j*2048, wn at wn*512
    const uint4* wbase = (const uint4*)g_Wb;
    const uint4* pW000 = wbase + 0 * 2048 + wn * 512 + lane;
    const uint4* pW011 = wbase + 1 * 2048 + wn * 512 + lane;
    const uint4* pW110 = wbase + 2 * 2048 + wn * 512 + lane;
    const uint4* pW101 = wbase + 3 * 2048 + wn * 512 + lane;

    float o0[2][4][4], aux[2][4][4];
    zacc(o0); zacc(aux);
    __syncthreads();   // X0 visible

    // ---- phase 1: o0 += (y0*X0)@W000 ; p011 = X0@W011  (X0 = slot0) ----
    dual64(sb + SLOT(0), pW000, pW011, y0h, o0, aux, wm, lane);

    // compress p011 to 16 half2 regs
    uint32_t p011h[16];
    #pragma unroll
    for (int mf = 0; mf < 2; ++mf)
        #pragma unroll
        for (int g = 0; g < 4; ++g) {
            p011h[mf * 8 + g * 2 + 0] = pack2(aux[mf][g][0], aux[mf][g][1]);
            p011h[mf * 8 + g * 2 + 1] = pack2(aux[mf][g][2], aux[mf][g][3]);
        }

    __syncthreads();                         // all warps done reading X0 (slot 0)
    fill_x1(sb, x, row0, n, wid, lane);      // X1_0/1/2 -> slots 1..3
    __syncwarp();                            // warp-local: fills visible to Z pass
    compute_z(sb, y, row0, n, wid, lane);    // Z -> slot 0 (same rows, same warp)
    __syncthreads();                         // all fills + Z visible CTA-wide

    // ---- phase 2a: o0 += Z @ W110  (Z prescaled with S3*y1, no hmul) ----
    single64<false>(sb + SLOT(0), pW110, y0h, o0, wm, lane);

    // ---- phase 2b: per i: o1_i = S3*y1_i*p011 + (S3*y0*X1_i)@W101 -> plane_i ----
    #pragma unroll 1
    for (int i = 0; i < 3; ++i) {
        float s1[2][2];
        #pragma unroll
        for (int mf = 0; mf < 2; ++mf)
            #pragma unroll
            for (int h = 0; h < 2; ++h)
                s1[mf][h] = S3 * yv[mf][h][1 + i];
        // seed aux = S3*y1_i * p011
        #pragma unroll
        for (int mf = 0; mf < 2; ++mf)
            #pragma unroll
            for (int g = 0; g < 4; ++g) {
                float2 plo = __half22float2(u2h(p011h[mf * 8 + g * 2 + 0]));
                float2 phi = __half22float2(u2h(p011h[mf * 8 + g * 2 + 1]));
                aux[mf][g][0] = s1[mf][0] * plo.x; aux[mf][g][1] = s1[mf][0] * plo.y;
                aux[mf][g][2] = s1[mf][1] * phi.x; aux[mf][g][3] = s1[mf][1] * phi.y;
            }
        single64<true>(sb + SLOT(1 + i), pW101, s3y0h, aux, wm, lane);
        __syncthreads();  // all warps done reading slot 1+i before overwrite
        // stage o1_i as f16 plane (pitch 132 halves) into slot 1+i
        #pragma unroll
        for (int mf = 0; mf < 2; ++mf)
            #pragma unroll
            for (int g = 0; g < 4; ++g) {
                uint32_t w0 = (uint32_t)(wn * 32 + g * 8 + 2 * (lane & 3));
                sts32(sb + SLOT(1 + i) + ((uint32_t)rl[mf] * 132u + w0) * 2u,
                      pack2(aux[mf][g][0], aux[mf][g][1]));
                sts32(sb + SLOT(1 + i) + ((uint32_t)(rl[mf] + 8) * 132u + w0) * 2u,
                      pack2(aux[mf][g][2], aux[mf][g][3]));
            }
    }

    // ---- store o0 + bias (float2, frag-direct) ----
    #pragma unroll
    for (int mf = 0; mf < 2; ++mf)
        #pragma unroll
        for (int g = 0; g < 4; ++g) {
            const int w0 = wn * 32 + g * 8 + 2 * (lane & 3);
            const float b0 = __ldg(bias + w0), b1 = __ldg(bias + w0 + 1);
            if (va[mf]) { float2 o = make_float2(o0[mf][g][0] + b0, o0[mf][g][1] + b1);
                          *(float2*)(out + gr0[mf] * 512 + w0) = o; }
            if (vb[mf]) { float2 o = make_float2(o0[mf][g][2] + b0, o0[mf][g][3] + b1);
                          *(float2*)(out + (gr0[mf] + 8) * 512 + w0) = o; }
        }
    __syncthreads();   // planes complete before final interleave

    // ---- final: interleave planes -> out[:, 128:512], warp-per-row STG.128 ----
    #pragma unroll 1
    for (int it = 0; it < 8; ++it) {
        int r = it * 8 + wid;
        long gr = row0 + r;
        if (gr < (long)n) {
            float4* dst = (float4*)(out + gr * 512 + 128);
            uint32_t pb = sb + (uint32_t)r * 264u;
            #pragma unroll
            for (int m = 0; m < 3; ++m) {
                uint32_t e0 = (uint32_t)(m * 128 + lane * 4);
                float o[4];
                #pragma unroll
                for (int j = 0; j < 4; ++j) {
                    uint32_t e = e0 + j;
                    uint32_t u = (e * 21846u) >> 16;   // e/3
                    uint32_t i = e - 3u * u;           // e%3
                    o[j] = us2f(lds16(pb + (1u + i) * SLOT_B + u * 2u));
                }
                dst[m * 32 + lane] = make_float4(o[0], o[1], o[2], o[3]);
            }
        }
    }
}

// ======================= launch =======================
extern "C" void kernel_launch(void* const* d_in, const int* in_sizes, int n_in,
                              void* d_out, int out_size) {
    const float* x    = (const float*)d_in[0];
    const float* y    = (const float*)d_in[1];
    const float* W000 = (const float*)d_in[2];
    const float* W011 = (const float*)d_in[3];
    const float* W101 = (const float*)d_in[4];
    const float* W110 = (const float*)d_in[5];
    const float* bias = (const float*)d_in[6];

    int n = in_sizes[1] / 4;  // y is (n, 4)
    if (n <= 0) return;

    o3tp_prep<<<128, 256>>>(W000, W011, W110, W101);

    cudaFuncSetAttribute(o3tp_main, cudaFuncAttributeMaxDynamicSharedMemorySize, SMEM_TOTAL);
    int grid = (n + 63) / 64;
    o3tp_main<<<grid, 256, SMEM_TOTAL>>>(x, y, bias, (float*)d_out, n);
}

// round 16
// speedup vs baseline: 1.6163x; 1.2039x over previous
#include <cuda_runtime.h>
#include <cuda_fp16.h>
#include <cstdint>

#define DINLINE __device__ __forceinline__
static __device__ constexpr float S3 = 0.57735026918962576451f;  // 1/sqrt(3)

// ======================= low-level helpers =======================
DINLINE uint32_t smem_u32(const void* p) {
    uint32_t a;
    asm("{ .reg .u64 t; cvta.to.shared.u64 t, %1; cvt.u32.u64 %0, t; }" : "=r"(a) : "l"(p));
    return a;
}
DINLINE void sts64(uint32_t a, uint32_t lo, uint32_t hi) {
    asm volatile("st.shared.v2.b32 [%0], {%1,%2};" :: "r"(a), "r"(lo), "r"(hi));
}
DINLINE void sts32(uint32_t a, uint32_t v) {
    asm volatile("st.shared.b32 [%0], %1;" :: "r"(a), "r"(v));
}
DINLINE void sts16(uint32_t a, unsigned short v) {
    asm volatile("st.shared.b16 [%0], %1;" :: "r"(a), "h"(v));
}
DINLINE unsigned short lds16(uint32_t a) {
    unsigned short v;
    asm volatile("ld.shared.b16 %0, [%1];" : "=h"(v) : "r"(a));
    return v;
}
DINLINE void ldmx4(uint32_t (&v)[4], uint32_t a) {
    asm volatile("ldmatrix.sync.aligned.m8n8.x4.shared.b16 {%0,%1,%2,%3}, [%4];"
                 : "=r"(v[0]), "=r"(v[1]), "=r"(v[2]), "=r"(v[3]) : "r"(a));
}
DINLINE void mmaf16(float (&d)[4], const uint32_t (&a)[4], uint32_t b0, uint32_t b1) {
    asm volatile(
        "mma.sync.aligned.m16n8k16.row.col.f32.f16.f16.f32 "
        "{%0,%1,%2,%3}, {%4,%5,%6,%7}, {%8,%9}, {%0,%1,%2,%3};"
        : "+f"(d[0]), "+f"(d[1]), "+f"(d[2]), "+f"(d[3])
        : "r"(a[0]), "r"(a[1]), "r"(a[2]), "r"(a[3]), "r"(b0), "r"(b1));
}
DINLINE uint32_t h2u(__half2 h) { return *reinterpret_cast<uint32_t*>(&h); }
DINLINE __half2  u2h(uint32_t u) { return *reinterpret_cast<__half2*>(&u); }
DINLINE uint32_t pack2(float a, float b) { return h2u(__floats2half2_rn(a, b)); }
DINLINE uint32_t hmul2u(uint32_t a, uint32_t b) { return h2u(__hmul2(u2h(a), u2h(b))); }
DINLINE unsigned short h2us(__half h) { return *reinterpret_cast<unsigned short*>(&h); }
DINLINE float us2f(unsigned short u) { __half h = *reinterpret_cast<__half*>(&u); return __half2float(h); }

// ======================= geometry =======================
// CTA 256 thr = 8 warps; tile 64 rows x 128 w-cols; warp tile 32x32 (grid 2m x 4n).
// X rows in smem: 128 f16 = 256 B = 16 chunks of 16 B, XOR swizzle chunk' = c ^ (row&7).
// Slot 0: X0, then X1_0; slots 1,2: X1_1/2; plane_i reuses slot i.
// Total smem 50.7 KB/CTA (2 CTAs -> 101 KB/SM) keeps L1D >= 128 KB for weights.
static constexpr uint32_t SLOT_B = 16896;   // raw X 16384 B; as plane 64 x 132h x 2B
#define SLOT(i) ((uint32_t)(i) * SLOT_B)
static constexpr uint32_t SMEM_TOTAL = 3 * SLOT_B;  // 50688

// Fragment-ordered global weights for direct lane-contiguous LDG.128:
// u32 index = ((j*4+wn)*8+kc)*256 + h*128 + lane*4 + e   (e in 0..3)
//   n = wn*32 + h*16 + ((e>>1)&1)*8 + (lane>>2)
//   k = kc*16 + (e&1)*8 + 2*(lane&3); value = half2(W[k][n], W[k+1][n])
// j: 0=W000, 1=W011, 2=W110, 3=W101 (source [k][n] = src[k*128+n])
__device__ __align__(16) uint32_t g_Wb[4 * 8192];

__global__ void o3tp_prep(const float* __restrict__ W000, const float* __restrict__ W011,
                          const float* __restrict__ W110, const float* __restrict__ W101) {
    int idx = blockIdx.x * blockDim.x + threadIdx.x;  // 0..32767
    int e = idx & 3, lane = (idx >> 2) & 31, h = (idx >> 7) & 1;
    int kc = (idx >> 8) & 7, wn = (idx >> 11) & 3, j = idx >> 13;
    int n = wn * 32 + h * 16 + ((e >> 1) & 1) * 8 + (lane >> 2);
    int k = kc * 16 + (e & 1) * 8 + 2 * (lane & 3);
    const float* src = (j == 0) ? W000 : (j == 1) ? W011 : (j == 2) ? W110 : W101;
    g_Wb[idx] = pack2(src[k * 128 + n], src[(k + 1) * 128 + n]);
}

// ======================= X fills (warp-per-row, lane-contiguous LDG) ==========
DINLINE void fill_x0(uint32_t slot, const float* __restrict__ x, long row0, int n,
                     int wid, int lane) {
    #pragma unroll
    for (int it = 0; it < 8; ++it) {
        int r = it * 8 + wid;
        long gr = row0 + r;
        float4 xv = (gr < (long)n) ? ((const float4*)(x + gr * 512))[lane]
                                   : make_float4(0.f, 0.f, 0.f, 0.f);
        uint32_t a = slot + (uint32_t)r * 256u
                   + ((((uint32_t)lane >> 1) ^ (uint32_t)(r & 7)) << 4)
                   + (uint32_t)(lane & 1) * 8u;
        sts64(a, pack2(xv.x, xv.y), pack2(xv.z, xv.w));
    }
}
DINLINE void fill_x1(uint32_t sb, const float* __restrict__ x, long row0, int n,
                     int wid, int lane) {
    #pragma unroll
    for (int it = 0; it < 8; ++it) {
        int r = it * 8 + wid;
        long gr = row0 + r;
        bool v = gr < (long)n;
        const float4* src = (const float4*)(x + gr * 512 + 128);
        uint32_t rowb = (uint32_t)r * 256u, s = (uint32_t)(r & 7);
        #pragma unroll
        for (int m = 0; m < 3; ++m) {
            float4 xv = v ? src[m * 32 + lane] : make_float4(0.f, 0.f, 0.f, 0.f);
            float el[4] = {xv.x, xv.y, xv.z, xv.w};
            #pragma unroll
            for (int j = 0; j < 4; ++j) {
                uint32_t e = (uint32_t)(m * 128 + lane * 4 + j);
                uint32_t u = (e * 21846u) >> 16;     // e/3
                uint32_t i = e - 3u * u;             // e%3
                uint32_t a = sb + i * SLOT_B + rowb
                           + ((((u >> 3) & 15u) ^ s) << 4) + (u & 7u) * 2u;
                sts16(a, h2us(__float2half_rn(el[j])));
            }
        }
    }
}

// ======================= dual GEMM (64x128 out, K=128, 2 B matrices) ==========
// acc1 += (c1 .* A) @ B1;  acc2 += (SC2 ? (c2 .* A) : A) @ B2. A read once.
template <bool SC2>
DINLINE void dual64(uint32_t xslot, const uint4* __restrict__ pB1,
                    const uint4* __restrict__ pB2,
                    const uint32_t (&c1)[2][2], const uint32_t (&c2)[2][2],
                    float (&acc1)[2][4][4], float (&acc2)[2][4][4],
                    int wm, int lane) {
    const uint32_t rA = (uint32_t)(wm * 32 + (lane & 15));
    const uint32_t cA = (uint32_t)((lane >> 4) & 1);
    const uint32_t sA = rA & 7;
    const uint32_t bA0 = xslot + rA * 256u, bA1 = bA0 + 4096u;
    #pragma unroll
    for (int kc = 0; kc < 8; ++kc) {
        uint32_t a0[4], a1[4];
        uint32_t ka = (((((uint32_t)kc << 1) | cA) ^ sA) << 4);
        ldmx4(a0, bA0 + ka); ldmx4(a1, bA1 + ka);
        uint4 p = pB1[kc * 64], q = pB1[kc * 64 + 32];
        uint4 r = pB2[kc * 64], s = pB2[kc * 64 + 32];
        uint32_t t0[4], t1[4];
        // scaled for B1
        t0[0] = hmul2u(a0[0], c1[0][0]); t0[1] = hmul2u(a0[1], c1[0][1]);
        t0[2] = hmul2u(a0[2], c1[0][0]); t0[3] = hmul2u(a0[3], c1[0][1]);
        t1[0] = hmul2u(a1[0], c1[1][0]); t1[1] = hmul2u(a1[1], c1[1][1]);
        t1[2] = hmul2u(a1[2], c1[1][0]); t1[3] = hmul2u(a1[3], c1[1][1]);
        mmaf16(acc1[0][0], t0, p.x, p.y); mmaf16(acc1[0][1], t0, p.z, p.w);
        mmaf16(acc1[0][2], t0, q.x, q.y); mmaf16(acc1[0][3], t0, q.z, q.w);
        mmaf16(acc1[1][0], t1, p.x, p.y); mmaf16(acc1[1][1], t1, p.z, p.w);
        mmaf16(acc1[1][2], t1, q.x, q.y); mmaf16(acc1[1][3], t1, q.z, q.w);
        // for B2: scaled only if SC2 (unscaled path is exact, used for p011)
        if (SC2) {
            t0[0] = hmul2u(a0[0], c2[0][0]); t0[1] = hmul2u(a0[1], c2[0][1]);
            t0[2] = hmul2u(a0[2], c2[0][0]); t0[3] = hmul2u(a0[3], c2[0][1]);
            t1[0] = hmul2u(a1[0], c2[1][0]); t1[1] = hmul2u(a1[1], c2[1][1]);
            t1[2] = hmul2u(a1[2], c2[1][0]); t1[3] = hmul2u(a1[3], c2[1][1]);
            mmaf16(acc2[0][0], t0, r.x, r.y); mmaf16(acc2[0][1], t0, r.z, r.w);
            mmaf16(acc2[0][2], t0, s.x, s.y); mmaf16(acc2[0][3], t0, s.z, s.w);
            mmaf16(acc2[1][0], t1, r.x, r.y); mmaf16(acc2[1][1], t1, r.z, r.w);
            mmaf16(acc2[1][2], t1, s.x, s.y); mmaf16(acc2[1][3], t1, s.z, s.w);
        } else {
            mmaf16(acc2[0][0], a0, r.x, r.y); mmaf16(acc2[0][1], a0, r.z, r.w);
            mmaf16(acc2[0][2], a0, s.x, s.y); mmaf16(acc2[0][3], a0, s.z, s.w);
            mmaf16(acc2[1][0], a1, r.x, r.y); mmaf16(acc2[1][1], a1, r.z, r.w);
            mmaf16(acc2[1][2], a1, s.x, s.y); mmaf16(acc2[1][3], a1, s.z, s.w);
        }
    }
}
DINLINE void zacc(float (&a)[2][4][4]) {
    #pragma unroll
    for (int m = 0; m < 2; ++m)
        #pragma unroll
        for (int g = 0; g < 4; ++g)
            #pragma unroll
            for (int e = 0; e < 4; ++e) a[m][g][e] = 0.0f;
}

// ======================= main kernel =======================
__global__ void __launch_bounds__(256, 2) o3tp_main(
    const float* __restrict__ x, const float* __restrict__ y,
    const float* __restrict__ bias, float* __restrict__ out, int n)
{
    extern __shared__ char smem[];
    const uint32_t sb = smem_u32(smem);
    const int t = threadIdx.x, lane = t & 31, wid = t >> 5;
    const int wm = wid & 1, wn = wid >> 1;
    const long row0 = (long)blockIdx.x * 64;

    fill_x0(sb + SLOT(0), x, row0, n, wid, lane);

    // per-thread c-frag rows; only y0-derived constants kept in registers.
    int rl[2]; long gr0[2]; bool va[2], vb[2];
    uint32_t y0h[2][2], s3y0h[2][2];
    #pragma unroll
    for (int mf = 0; mf < 2; ++mf) {
        rl[mf] = wm * 32 + mf * 16 + (lane >> 2);
        gr0[mf] = row0 + rl[mf];
        va[mf] = gr0[mf] < (long)n;
        vb[mf] = gr0[mf] + 8 < (long)n;
        float y0a = va[mf] ? __ldg(y + gr0[mf] * 4) : 0.f;
        float y0b = vb[mf] ? __ldg(y + (gr0[mf] + 8) * 4) : 0.f;
        y0h[mf][0]   = h2u(__float2half2_rn(y0a));
        y0h[mf][1]   = h2u(__float2half2_rn(y0b));
        s3y0h[mf][0] = h2u(__float2half2_rn(S3 * y0a));
        s3y0h[mf][1] = h2u(__float2half2_rn(S3 * y0b));
    }

    // warp B-fragment pointers (uint4 units): matrix j at j*2048, wn at wn*512
    const uint4* wbase = (const uint4*)g_Wb;
    const uint4* pW000 = wbase + 0 * 2048 + wn * 512 + lane;
    const uint4* pW011 = wbase + 1 * 2048 + wn * 512 + lane;
    const uint4* pW110 = wbase + 2 * 2048 + wn * 512 + lane;
    const uint4* pW101 = wbase + 3 * 2048 + wn * 512 + lane;

    float o0[2][4][4], aux[2][4][4];
    zacc(o0); zacc(aux);
    __syncthreads();   // X0 visible

    // ---- phase 1: o0 += (y0*X0)@W000 ; p011 = X0@W011 (raw A, exact) ----
    dual64<false>(sb + SLOT(0), pW000, pW011, y0h, y0h, o0, aux, wm, lane);

    // compress p011 to 16 half2 regs
    uint32_t p011h[16];
    #pragma unroll
    for (int mf = 0; mf < 2; ++mf)
        #pragma unroll
        for (int g = 0; g < 4; ++g) {
            p011h[mf * 8 + g * 2 + 0] = pack2(aux[mf][g][0], aux[mf][g][1]);
            p011h[mf * 8 + g * 2 + 1] = pack2(aux[mf][g][2], aux[mf][g][3]);
        }

    __syncthreads();                        // all warps done reading X0
    fill_x1(sb, x, row0, n, wid, lane);     // X1_0/1/2 -> slots 0/1/2
    __syncthreads();                        // X1 visible

    // ---- phase 2: per i: o0 += (S3*y1_i*X1_i)@W110 ;
    //               o1_i = S3*y1_i*p011 + (S3*y0*X1_i)@W101 -> plane_i (slot i) ----
    #pragma unroll 1
    for (int i = 0; i < 3; ++i) {
        // reload y1_i per iteration (L1-hot) instead of holding 12 regs
        float s1[2][2];
        uint32_t c1[2][2];
        #pragma unroll
        for (int mf = 0; mf < 2; ++mf) {
            float y1a = va[mf] ? __ldg(y + gr0[mf] * 4 + 1 + i) : 0.f;
            float y1b = vb[mf] ? __ldg(y + (gr0[mf] + 8) * 4 + 1 + i) : 0.f;
            s1[mf][0] = S3 * y1a; s1[mf][1] = S3 * y1b;
            c1[mf][0] = h2u(__float2half2_rn(s1[mf][0]));
            c1[mf][1] = h2u(__float2half2_rn(s1[mf][1]));
        }
        // seed aux = S3*y1_i * p011
        #pragma unroll
        for (int mf = 0; mf < 2; ++mf)
            #pragma unroll
            for (int g = 0; g < 4; ++g) {
                float2 plo = __half22float2(u2h(p011h[mf * 8 + g * 2 + 0]));
                float2 phi = __half22float2(u2h(p011h[mf * 8 + g * 2 + 1]));
                aux[mf][g][0] = s1[mf][0] * plo.x; aux[mf][g][1] = s1[mf][0] * plo.y;
                aux[mf][g][2] = s1[mf][1] * phi.x; aux[mf][g][3] = s1[mf][1] * phi.y;
            }
        dual64<true>(sb + SLOT(i), pW110, pW101, c1, s3y0h, o0, aux, wm, lane);
        __syncthreads();  // all warps done reading slot i before overwrite
        // stage o1_i as f16 plane (pitch 132 halves)
        #pragma unroll
        for (int mf = 0; mf < 2; ++mf)
            #pragma unroll
            for (int g = 0; g < 4; ++g) {
                uint32_t w0 = (uint32_t)(wn * 32 + g * 8 + 2 * (lane & 3));
                sts32(sb + SLOT(i) + ((uint32_t)rl[mf] * 132u + w0) * 2u,
                      pack2(aux[mf][g][0], aux[mf][g][1]));
                sts32(sb + SLOT(i) + ((uint32_t)(rl[mf] + 8) * 132u + w0) * 2u,
                      pack2(aux[mf][g][2], aux[mf][g][3]));
            }
    }

    // ---- store o0 + bias (float2, frag-direct) ----
    #pragma unroll
    for (int mf = 0; mf < 2; ++mf)
        #pragma unroll
        for (int g = 0; g < 4; ++g) {
            const int w0 = wn * 32 + g * 8 + 2 * (lane & 3);
            const float b0 = __ldg(bias + w0), b1 = __ldg(bias + w0 + 1);
            if (va[mf]) { float2 o = make_float2(o0[mf][g][0] + b0, o0[mf][g][1] + b1);
                          *(float2*)(out + gr0[mf] * 512 + w0) = o; }
            if (vb[mf]) { float2 o = make_float2(o0[mf][g][2] + b0, o0[mf][g][3] + b1);
                          *(float2*)(out + (gr0[mf] + 8) * 512 + w0) = o; }
        }
    __syncthreads();   // planes complete before final interleave

    // ---- final: interleave planes -> out[:, 128:512], warp-per-row STG.128 ----
    #pragma unroll 1
    for (int it = 0; it < 8; ++it) {
        int r = it * 8 + wid;
        long gr = row0 + r;
        if (gr < (long)n) {
            float4* dst = (float4*)(out + gr * 512 + 128);
            uint32_t pb = sb + (uint32_t)r * 264u;
            #pragma unroll
            for (int m = 0; m < 3; ++m) {
                uint32_t e0 = (uint32_t)(m * 128 + lane * 4);
                float o[4];
                #pragma unroll
                for (int j = 0; j < 4; ++j) {
                    uint32_t e = e0 + j;
                    uint32_t u = (e * 21846u) >> 16;   // e/3
                    uint32_t i = e - 3u * u;           // e%3
                    o[j] = us2f(lds16(pb + i * SLOT_B + u * 2u));
                }
                dst[m * 32 + lane] = make_float4(o[0], o[1], o[2], o[3]);
            }
        }
    }
}

// ======================= launch =======================
extern "C" void kernel_launch(void* const* d_in, const int* in_sizes, int n_in,
                              void* d_out, int out_size) {
    const float* x    = (const float*)d_in[0];
    const float* y    = (const float*)d_in[1];
    const float* W000 = (const float*)d_in[2];
    const float* W011 = (const float*)d_in[3];
    const float* W101 = (const float*)d_in[4];
    const float* W110 = (const float*)d_in[5];
    const float* bias = (const float*)d_in[6];

    int n = in_sizes[1] / 4;  // y is (n, 4)
    if (n <= 0) return;

    o3tp_prep<<<128, 256>>>(W000, W011, W110, W101);

    cudaFuncSetAttribute(o3tp_main, cudaFuncAttributeMaxDynamicSharedMemorySize, SMEM_TOTAL);
    int grid = (n + 63) / 64;
    o3tp_main<<<grid, 256, SMEM_TOTAL>>>(x, y, bias, (float*)d_out, n);
}

// round 17
// speedup vs baseline: 1.6252x; 1.0055x over previous
#include <cuda_runtime.h>
#include <cuda_fp16.h>
#include <cstdint>

#define DINLINE __device__ __forceinline__
static __device__ constexpr float S3 = 0.57735026918962576451f;  // 1/sqrt(3)

// ======================= low-level helpers =======================
DINLINE uint32_t smem_u32(const void* p) {
    uint32_t a;
    asm("{ .reg .u64 t; cvta.to.shared.u64 t, %1; cvt.u32.u64 %0, t; }" : "=r"(a) : "l"(p));
    return a;
}
DINLINE void sts64(uint32_t a, uint32_t lo, uint32_t hi) {
    asm volatile("st.shared.v2.b32 [%0], {%1,%2};" :: "r"(a), "r"(lo), "r"(hi));
}
DINLINE void sts32(uint32_t a, uint32_t v) {
    asm volatile("st.shared.b32 [%0], %1;" :: "r"(a), "r"(v));
}
DINLINE void sts16(uint32_t a, unsigned short v) {
    asm volatile("st.shared.b16 [%0], %1;" :: "r"(a), "h"(v));
}
DINLINE unsigned short lds16(uint32_t a) {
    unsigned short v;
    asm volatile("ld.shared.b16 %0, [%1];" : "=h"(v) : "r"(a));
    return v;
}
DINLINE void ldmx4(uint32_t (&v)[4], uint32_t a) {
    asm volatile("ldmatrix.sync.aligned.m8n8.x4.shared.b16 {%0,%1,%2,%3}, [%4];"
                 : "=r"(v[0]), "=r"(v[1]), "=r"(v[2]), "=r"(v[3]) : "r"(a));
}
DINLINE void mmaf16(float (&d)[4], const uint32_t (&a)[4], uint32_t b0, uint32_t b1) {
    asm volatile(
        "mma.sync.aligned.m16n8k16.row.col.f32.f16.f16.f32 "
        "{%0,%1,%2,%3}, {%4,%5,%6,%7}, {%8,%9}, {%0,%1,%2,%3};"
        : "+f"(d[0]), "+f"(d[1]), "+f"(d[2]), "+f"(d[3])
        : "r"(a[0]), "r"(a[1]), "r"(a[2]), "r"(a[3]), "r"(b0), "r"(b1));
}
// x tile loads: cg = L2-only. x is read exactly once -> keep it OUT of L1 so the
// 128 KB weight-fragment set stays L1-resident (the hot path).
DINLINE float4 ldg128f_cg(const float4* p) {
    float4 v;
    asm volatile("ld.global.cg.v4.f32 {%0,%1,%2,%3}, [%4];"
                 : "=f"(v.x), "=f"(v.y), "=f"(v.z), "=f"(v.w) : "l"(p));
    return v;
}
DINLINE uint32_t h2u(__half2 h) { return *reinterpret_cast<uint32_t*>(&h); }
DINLINE __half2  u2h(uint32_t u) { return *reinterpret_cast<__half2*>(&u); }
DINLINE uint32_t pack2(float a, float b) { return h2u(__floats2half2_rn(a, b)); }
DINLINE uint32_t hmul2u(uint32_t a, uint32_t b) { return h2u(__hmul2(u2h(a), u2h(b))); }
DINLINE unsigned short h2us(__half h) { return *reinterpret_cast<unsigned short*>(&h); }
DINLINE float us2f(unsigned short u) { __half h = *reinterpret_cast<__half*>(&u); return __half2float(h); }

// ======================= geometry =======================
// CTA 256 thr = 8 warps; tile 64 rows x 128 w-cols; warp tile 32x32 (grid 2m x 4n).
// X rows in smem: 128 f16 = 256 B = 16 chunks of 16 B, XOR swizzle chunk' = c ^ (row&7).
// Slot 0: X0, then X1_0; slots 1,2: X1_1/2; plane_i reuses slot i.
// Total smem 50.7 KB/CTA (2 CTAs -> 101 KB/SM) keeps L1D ~127 KB for weights.
static constexpr uint32_t SLOT_B = 16896;   // raw X 16384 B; as plane 64 x 132h x 2B
#define SLOT(i) ((uint32_t)(i) * SLOT_B)
static constexpr uint32_t SMEM_TOTAL = 3 * SLOT_B;  // 50688

// Fragment-ordered global weights for direct lane-contiguous LDG.128:
// u32 index = ((j*4+wn)*8+kc)*256 + h*128 + lane*4 + e   (e in 0..3)
//   n = wn*32 + h*16 + ((e>>1)&1)*8 + (lane>>2)
//   k = kc*16 + (e&1)*8 + 2*(lane&3); value = half2(W[k][n], W[k+1][n])
// j: 0=W000, 1=W011, 2=W110, 3=W101 (source [k][n] = src[k*128+n])
__device__ __align__(16) uint32_t g_Wb[4 * 8192];

__global__ void o3tp_prep(const float* __restrict__ W000, const float* __restrict__ W011,
                          const float* __restrict__ W110, const float* __restrict__ W101) {
    int idx = blockIdx.x * blockDim.x + threadIdx.x;  // 0..32767
    int e = idx & 3, lane = (idx >> 2) & 31, h = (idx >> 7) & 1;
    int kc = (idx >> 8) & 7, wn = (idx >> 11) & 3, j = idx >> 13;
    int n = wn * 32 + h * 16 + ((e >> 1) & 1) * 8 + (lane >> 2);
    int k = kc * 16 + (e & 1) * 8 + 2 * (lane & 3);
    const float* src = (j == 0) ? W000 : (j == 1) ? W011 : (j == 2) ? W110 : W101;
    g_Wb[idx] = pack2(src[k * 128 + n], src[(k + 1) * 128 + n]);
}

// ======================= X fills (warp-per-row, lane-contiguous cg LDG) =======
DINLINE void fill_x0(uint32_t slot, const float* __restrict__ x, long row0, int n,
                     int wid, int lane) {
    #pragma unroll
    for (int it = 0; it < 8; ++it) {
        int r = it * 8 + wid;
        long gr = row0 + r;
        float4 xv = (gr < (long)n) ? ldg128f_cg((const float4*)(x + gr * 512) + lane)
                                   : make_float4(0.f, 0.f, 0.f, 0.f);
        uint32_t a = slot + (uint32_t)r * 256u
                   + ((((uint32_t)lane >> 1) ^ (uint32_t)(r & 7)) << 4)
                   + (uint32_t)(lane & 1) * 8u;
        sts64(a, pack2(xv.x, xv.y), pack2(xv.z, xv.w));
    }
}
DINLINE void fill_x1(uint32_t sb, const float* __restrict__ x, long row0, int n,
                     int wid, int lane) {
    #pragma unroll
    for (int it = 0; it < 8; ++it) {
        int r = it * 8 + wid;
        long gr = row0 + r;
        bool v = gr < (long)n;
        const float4* src = (const float4*)(x + gr * 512 + 128);
        uint32_t rowb = (uint32_t)r * 256u, s = (uint32_t)(r & 7);
        #pragma unroll
        for (int m = 0; m < 3; ++m) {
            float4 xv = v ? ldg128f_cg(src + m * 32 + lane)
                          : make_float4(0.f, 0.f, 0.f, 0.f);
            float el[4] = {xv.x, xv.y, xv.z, xv.w};
            #pragma unroll
            for (int j = 0; j < 4; ++j) {
                uint32_t e = (uint32_t)(m * 128 + lane * 4 + j);
                uint32_t u = (e * 21846u) >> 16;     // e/3
                uint32_t i = e - 3u * u;             // e%3
                uint32_t a = sb + i * SLOT_B + rowb
                           + ((((u >> 3) & 15u) ^ s) << 4) + (u & 7u) * 2u;
                sts16(a, h2us(__float2half_rn(el[j])));
            }
        }
    }
}

// ======================= dual GEMM (64x128 out, K=128, 2 B matrices) ==========
// acc1 += (c1 .* A) @ B1;  acc2 += (SC2 ? (c2 .* A) : A) @ B2. A read once.
template <bool SC2>
DINLINE void dual64(uint32_t xslot, const uint4* __restrict__ pB1,
                    const uint4* __restrict__ pB2,
                    const uint32_t (&c1)[2][2], const uint32_t (&c2)[2][2],
                    float (&acc1)[2][4][4], float (&acc2)[2][4][4],
                    int wm, int lane) {
    const uint32_t rA = (uint32_t)(wm * 32 + (lane & 15));
    const uint32_t cA = (uint32_t)((lane >> 4) & 1);
    const uint32_t sA = rA & 7;
    const uint32_t bA0 = xslot + rA * 256u, bA1 = bA0 + 4096u;
    #pragma unroll
    for (int kc = 0; kc < 8; ++kc) {
        uint32_t a0[4], a1[4];
        uint32_t ka = (((((uint32_t)kc << 1) | cA) ^ sA) << 4);
        ldmx4(a0, bA0 + ka); ldmx4(a1, bA1 + ka);
        uint4 p = pB1[kc * 64], q = pB1[kc * 64 + 32];
        uint4 r = pB2[kc * 64], s = pB2[kc * 64 + 32];
        uint32_t t0[4], t1[4];
        // scaled for B1
        t0[0] = hmul2u(a0[0], c1[0][0]); t0[1] = hmul2u(a0[1], c1[0][1]);
        t0[2] = hmul2u(a0[2], c1[0][0]); t0[3] = hmul2u(a0[3], c1[0][1]);
        t1[0] = hmul2u(a1[0], c1[1][0]); t1[1] = hmul2u(a1[1], c1[1][1]);
        t1[2] = hmul2u(a1[2], c1[1][0]); t1[3] = hmul2u(a1[3], c1[1][1]);
        mmaf16(acc1[0][0], t0, p.x, p.y); mmaf16(acc1[0][1], t0, p.z, p.w);
        mmaf16(acc1[0][2], t0, q.x, q.y); mmaf16(acc1[0][3], t0, q.z, q.w);
        mmaf16(acc1[1][0], t1, p.x, p.y); mmaf16(acc1[1][1], t1, p.z, p.w);
        mmaf16(acc1[1][2], t1, q.x, q.y); mmaf16(acc1[1][3], t1, q.z, q.w);
        // for B2: scaled only if SC2 (unscaled path is exact, used for p011)
        if (SC2) {
            t0[0] = hmul2u(a0[0], c2[0][0]); t0[1] = hmul2u(a0[1], c2[0][1]);
            t0[2] = hmul2u(a0[2], c2[0][0]); t0[3] = hmul2u(a0[3], c2[0][1]);
            t1[0] = hmul2u(a1[0], c2[1][0]); t1[1] = hmul2u(a1[1], c2[1][1]);
            t1[2] = hmul2u(a1[2], c2[1][0]); t1[3] = hmul2u(a1[3], c2[1][1]);
            mmaf16(acc2[0][0], t0, r.x, r.y); mmaf16(acc2[0][1], t0, r.z, r.w);
            mmaf16(acc2[0][2], t0, s.x, s.y); mmaf16(acc2[0][3], t0, s.z, s.w);
            mmaf16(acc2[1][0], t1, r.x, r.y); mmaf16(acc2[1][1], t1, r.z, r.w);
            mmaf16(acc2[1][2], t1, s.x, s.y); mmaf16(acc2[1][3], t1, s.z, s.w);
        } else {
            mmaf16(acc2[0][0], a0, r.x, r.y); mmaf16(acc2[0][1], a0, r.z, r.w);
            mmaf16(acc2[0][2], a0, s.x, s.y); mmaf16(acc2[0][3], a0, s.z, s.w);
            mmaf16(acc2[1][0], a1, r.x, r.y); mmaf16(acc2[1][1], a1, r.z, r.w);
            mmaf16(acc2[1][2], a1, s.x, s.y); mmaf16(acc2[1][3], a1, s.z, s.w);
        }
    }
}
DINLINE void zacc(float (&a)[2][4][4]) {
    #pragma unroll
    for (int m = 0; m < 2; ++m)
        #pragma unroll
        for (int g = 0; g < 4; ++g)
            #pragma unroll
            for (int e = 0; e < 4; ++e) a[m][g][e] = 0.0f;
}

// ======================= main kernel =======================
__global__ void __launch_bounds__(256, 2) o3tp_main(
    const float* __restrict__ x, const float* __restrict__ y,
    const float* __restrict__ bias, float* __restrict__ out, int n)
{
    extern __shared__ char smem[];
    const uint32_t sb = smem_u32(smem);
    const int t = threadIdx.x, lane = t & 31, wid = t >> 5;
    const int wm = wid & 1, wn = wid >> 1;
    const long row0 = (long)blockIdx.x * 64;

    fill_x0(sb + SLOT(0), x, row0, n, wid, lane);

    // per-thread c-frag rows; only y0-derived constants kept in registers.
    int rl[2]; long gr0[2]; bool va[2], vb[2];
    uint32_t y0h[2][2], s3y0h[2][2];
    #pragma unroll
    for (int mf = 0; mf < 2; ++mf) {
        rl[mf] = wm * 32 + mf * 16 + (lane >> 2);
        gr0[mf] = row0 + rl[mf];
        va[mf] = gr0[mf] < (long)n;
        vb[mf] = gr0[mf] + 8 < (long)n;
        float y0a = va[mf] ? __ldg(y + gr0[mf] * 4) : 0.f;
        float y0b = vb[mf] ? __ldg(y + (gr0[mf] + 8) * 4) : 0.f;
        y0h[mf][0]   = h2u(__float2half2_rn(y0a));
        y0h[mf][1]   = h2u(__float2half2_rn(y0b));
        s3y0h[mf][0] = h2u(__float2half2_rn(S3 * y0a));
        s3y0h[mf][1] = h2u(__float2half2_rn(S3 * y0b));
    }

    // warp B-fragment pointers (uint4 units): matrix j at j*2048, wn at wn*512
    const uint4* wbase = (const uint4*)g_Wb;
    const uint4* pW000 = wbase + 0 * 2048 + wn * 512 + lane;
    const uint4* pW011 = wbase + 1 * 2048 + wn * 512 + lane;
    const uint4* pW110 = wbase + 2 * 2048 + wn * 512 + lane;
    const uint4* pW101 = wbase + 3 * 2048 + wn * 512 + lane;

    float o0[2][4][4], aux[2][4][4];
    zacc(o0); zacc(aux);
    __syncthreads();   // X0 visible

    // ---- phase 1: o0 += (y0*X0)@W000 ; p011 = X0@W011 (raw A, exact) ----
    dual64<false>(sb + SLOT(0), pW000, pW011, y0h, y0h, o0, aux, wm, lane);

    // compress p011 to 16 half2 regs
    uint32_t p011h[16];
    #pragma unroll
    for (int mf = 0; mf < 2; ++mf)
        #pragma unroll
        for (int g = 0; g < 4; ++g) {
            p011h[mf * 8 + g * 2 + 0] = pack2(aux[mf][g][0], aux[mf][g][1]);
            p011h[mf * 8 + g * 2 + 1] = pack2(aux[mf][g][2], aux[mf][g][3]);
        }

    __syncthreads();                        // all warps done reading X0
    fill_x1(sb, x, row0, n, wid, lane);     // X1_0/1/2 -> slots 0/1/2
    __syncthreads();                        // X1 visible

    // ---- phase 2: per i: o0 += (S3*y1_i*X1_i)@W110 ;
    //               o1_i = S3*y1_i*p011 + (S3*y0*X1_i)@W101 -> plane_i (slot i) ----
    #pragma unroll 1
    for (int i = 0; i < 3; ++i) {
        // reload y1_i per iteration (L1-hot) instead of holding 12 regs
        float s1[2][2];
        uint32_t c1[2][2];
        #pragma unroll
        for (int mf = 0; mf < 2; ++mf) {
            float y1a = va[mf] ? __ldg(y + gr0[mf] * 4 + 1 + i) : 0.f;
            float y1b = vb[mf] ? __ldg(y + (gr0[mf] + 8) * 4 + 1 + i) : 0.f;
            s1[mf][0] = S3 * y1a; s1[mf][1] = S3 * y1b;
            c1[mf][0] = h2u(__float2half2_rn(s1[mf][0]));
            c1[mf][1] = h2u(__float2half2_rn(s1[mf][1]));
        }
        // seed aux = S3*y1_i * p011
        #pragma unroll
        for (int mf = 0; mf < 2; ++mf)
            #pragma unroll
            for (int g = 0; g < 4; ++g) {
                float2 plo = __half22float2(u2h(p011h[mf * 8 + g * 2 + 0]));
                float2 phi = __half22float2(u2h(p011h[mf * 8 + g * 2 + 1]));
                aux[mf][g][0] = s1[mf][0] * plo.x; aux[mf][g][1] = s1[mf][0] * plo.y;
                aux[mf][g][2] = s1[mf][1] * phi.x; aux[mf][g][3] = s1[mf][1] * phi.y;
            }
        dual64<true>(sb + SLOT(i), pW110, pW101, c1, s3y0h, o0, aux, wm, lane);
        __syncthreads();  // all warps done reading slot i before overwrite
        // stage o1_i as f16 plane (pitch 132 halves)
        #pragma unroll
        for (int mf = 0; mf < 2; ++mf)
            #pragma unroll
            for (int g = 0; g < 4; ++g) {
                uint32_t w0 = (uint32_t)(wn * 32 + g * 8 + 2 * (lane & 3));
                sts32(sb + SLOT(i) + ((uint32_t)rl[mf] * 132u + w0) * 2u,
                      pack2(aux[mf][g][0], aux[mf][g][1]));
                sts32(sb + SLOT(i) + ((uint32_t)(rl[mf] + 8) * 132u + w0) * 2u,
                      pack2(aux[mf][g][2], aux[mf][g][3]));
            }
    }

    // ---- store o0 + bias (float2, frag-direct) ----
    #pragma unroll
    for (int mf = 0; mf < 2; ++mf)
        #pragma unroll
        for (int g = 0; g < 4; ++g) {
            const int w0 = wn * 32 + g * 8 + 2 * (lane & 3);
            const float b0 = __ldg(bias + w0), b1 = __ldg(bias + w0 + 1);
            if (va[mf]) { float2 o = make_float2(o0[mf][g][0] + b0, o0[mf][g][1] + b1);
                          *(float2*)(out + gr0[mf] * 512 + w0) = o; }
            if (vb[mf]) { float2 o = make_float2(o0[mf][g][2] + b0, o0[mf][g][3] + b1);
                          *(float2*)(out + (gr0[mf] + 8) * 512 + w0) = o; }
        }
    __syncthreads();   // planes complete before final interleave

    // ---- final: interleave planes -> out[:, 128:512], warp-per-row STG.128 ----
    #pragma unroll 1
    for (int it = 0; it < 8; ++it) {
        int r = it * 8 + wid;
        long gr = row0 + r;
        if (gr < (long)n) {
            float4* dst = (float4*)(out + gr * 512 + 128);
            uint32_t pb = sb + (uint32_t)r * 264u;
            #pragma unroll
            for (int m = 0; m < 3; ++m) {
                uint32_t e0 = (uint32_t)(m * 128 + lane * 4);
                float o[4];
                #pragma unroll
                for (int j = 0; j < 4; ++j) {
                    uint32_t e = e0 + j;
                    uint32_t u = (e * 21846u) >> 16;   // e/3
                    uint32_t i = e - 3u * u;           // e%3
                    o[j] = us2f(lds16(pb + i * SLOT_B + u * 2u));
                }
                dst[m * 32 + lane] = make_float4(o[0], o[1], o[2], o[3]);
            }
        }
    }
}

// ======================= launch =======================
extern "C" void kernel_launch(void* const* d_in, const int* in_sizes, int n_in,
                              void* d_out, int out_size) {
    const float* x    = (const float*)d_in[0];
    const float* y    = (const float*)d_in[1];
    const float* W000 = (const float*)d_in[2];
    const float* W011 = (const float*)d_in[3];
    const float* W101 = (const float*)d_in[4];
    const float* W110 = (const float*)d_in[5];
    const float* bias = (const float*)d_in[6];

    int n = in_sizes[1] / 4;  // y is (n, 4)
    if (n <= 0) return;

    o3tp_prep<<<128, 256>>>(W000, W011, W110, W101);

    cudaFuncSetAttribute(o3tp_main, cudaFuncAttributeMaxDynamicSharedMemorySize, SMEM_TOTAL);
    int grid = (n + 63) / 64;
    o3tp_main<<<grid, 256, SMEM_TOTAL>>>(x, y, bias, (float*)d_out, n);
}